// round 2
// baseline (speedup 1.0000x reference)
#include <cuda_runtime.h>
#include <cuda_bf16.h>

#define Bb 2
#define Vv 100000
#define Mm 200000          // B*V
#define Nn 8192
#define Kk 8
#define Cc 64
#define GX 128
#define GY 128
#define GZ 16
#define CELLS (GX*GY*GZ)   // 262144
#define EPSF 1e-5f
#define NSTATB 200
#define ROWS_PER_STATB (Mm / NSTATB)  // 1000

// ---------------- scratch (device globals; no runtime alloc allowed) ----------
// NOTE: these are ONLY referenced from device code (never passed as kernel args
// from host — host-side symbol addresses are the host shadow, not the device array).
__device__ int   g_grid[Bb * CELLS];          // 2 MB
__device__ int   g_nbr[Mm * 27];              // 21.6 MB
__device__ float g_f1[Mm * Cc];               // 51.2 MB
__device__ float g_f2[Mm * Cc];               // 51.2 MB
__device__ float g_part[NSTATB * 128];        // per-block [sum(64), sumsq(64)]
__device__ float g_scale[Cc];
__device__ float g_shift[Cc];

// ---------------- grid init / scatter / neighbor table ------------------------
__global__ void init_grid_kernel() {
    int i = blockIdx.x * blockDim.x + threadIdx.x;
    if (i < Bb * CELLS) g_grid[i] = -1;
}

__global__ void scatter_kernel(const int* __restrict__ coords) {
    int m = blockIdx.x * blockDim.x + threadIdx.x;
    if (m >= Mm) return;
    int b = m / Vv;
    int cx = coords[m * 3 + 0];
    int cy = coords[m * 3 + 1];
    int cz = coords[m * 3 + 2];
    g_grid[b * CELLS + (cx * GY + cy) * GZ + cz] = m;
}

__global__ void build_nbr_kernel(const int* __restrict__ coords) {
    int m = blockIdx.x * blockDim.x + threadIdx.x;
    if (m >= Mm) return;
    int b = m / Vv;
    int cx = coords[m * 3 + 0];
    int cy = coords[m * 3 + 1];
    int cz = coords[m * 3 + 2];
    const int* gb = g_grid + b * CELLS;
    int k = 0;
    #pragma unroll
    for (int dx = -1; dx <= 1; dx++)
      #pragma unroll
      for (int dy = -1; dy <= 1; dy++)
        #pragma unroll
        for (int dz = -1; dz <= 1; dz++) {
            int nx = cx + dx, ny = cy + dy, nz = cz + dz;
            int idx = -1;
            if (nx >= 0 && nx < GX && ny >= 0 && ny < GY && nz >= 0 && nz < GZ)
                idx = gb[(nx * GY + ny) * GZ + nz];
            g_nbr[m * 27 + k] = idx;
            k++;
        }
}

// ---------------- subm conv: 64-row tile, 27 offsets, smem GEMM ----------------
// blockDim = 256. Each thread computes a 4x4 register tile of the 64x64 output.
// src_sel: 0 = ext (voxel_feature input), 1 = g_f1.  dst_sel: 1 = g_f1, 2 = g_f2.
#define NF_STRIDE 68
__global__ __launch_bounds__(256) void conv_kernel(const float* __restrict__ ext,
                                                   const float* __restrict__ Wall,
                                                   int src_sel, int dst_sel) {
    __shared__ float s_W[64 * 64];
    __shared__ float s_nf[64 * NF_STRIDE];
    __shared__ int   s_idx[64];

    const float* feats = (src_sel == 0) ? ext : g_f1;
    float*       out   = (dst_sel == 1) ? g_f1 : g_f2;

    const int tid  = threadIdx.x;
    const int row0 = blockIdx.x * 64;
    const int tr   = tid >> 4;   // 0..15 -> rows tr*4..tr*4+3
    const int tc   = tid & 15;   // 0..15 -> cols tc*4..tc*4+3

    float acc[4][4];
    #pragma unroll
    for (int i = 0; i < 4; i++)
        #pragma unroll
        for (int j = 0; j < 4; j++) acc[i][j] = 0.f;

    const float4* f4 = reinterpret_cast<const float4*>(feats);

    for (int k = 0; k < 27; k++) {
        __syncthreads();   // previous compute done; safe to overwrite smem
        if (tid < 64) s_idx[tid] = g_nbr[(row0 + tid) * 27 + k];
        const float4* W4  = reinterpret_cast<const float4*>(Wall + k * 4096);
        float4*       sW4 = reinterpret_cast<float4*>(s_W);
        #pragma unroll
        for (int i = 0; i < 4; i++) sW4[tid + i * 256] = W4[tid + i * 256];
        __syncthreads();   // s_idx ready
        #pragma unroll
        for (int i = 0; i < 4; i++) {
            int e   = tid + i * 256;
            int row = e >> 4, seg = e & 15;
            int idx = s_idx[row];
            float4 v = make_float4(0.f, 0.f, 0.f, 0.f);
            if (idx >= 0) v = f4[idx * 16 + seg];
            *reinterpret_cast<float4*>(&s_nf[row * NF_STRIDE + seg * 4]) = v;
        }
        __syncthreads();   // tiles ready
        #pragma unroll
        for (int j = 0; j < 64; j++) {
            float4 bv = *reinterpret_cast<const float4*>(&s_W[j * 64 + tc * 4]);
            #pragma unroll
            for (int i = 0; i < 4; i++) {
                float a = s_nf[(tr * 4 + i) * NF_STRIDE + j];
                acc[i][0] += a * bv.x;
                acc[i][1] += a * bv.y;
                acc[i][2] += a * bv.z;
                acc[i][3] += a * bv.w;
            }
        }
    }
    #pragma unroll
    for (int i = 0; i < 4; i++) {
        float4 v = make_float4(acc[i][0], acc[i][1], acc[i][2], acc[i][3]);
        reinterpret_cast<float4*>(out)[((row0 + tr * 4 + i) * 64 + tc * 4) >> 2] = v;
    }
}

// ---------------- BN stats (deterministic 2-stage reduction) -------------------
__global__ __launch_bounds__(256) void stats_kernel(int sel) {
    __shared__ float ssum[256];
    __shared__ float ssq[256];
    const float* x = (sel == 1) ? g_f1 : g_f2;
    const int tid = threadIdx.x;
    const int c   = tid & 63;
    const int g   = tid >> 6;           // 0..3
    const int r0  = blockIdx.x * ROWS_PER_STATB;
    float s = 0.f, q = 0.f;
    for (int r = g; r < ROWS_PER_STATB; r += 4) {
        float v = x[(r0 + r) * 64 + c];
        s += v;
        q += v * v;
    }
    ssum[tid] = s; ssq[tid] = q;
    __syncthreads();
    if (g == 0) {
        float S = ssum[c] + ssum[64 + c] + ssum[128 + c] + ssum[192 + c];
        float Q = ssq[c]  + ssq[64 + c]  + ssq[128 + c]  + ssq[192 + c];
        g_part[blockIdx.x * 128 + c]      = S;
        g_part[blockIdx.x * 128 + 64 + c] = Q;
    }
}

__global__ void finalize_bn_kernel(const float* __restrict__ gamma,
                                   const float* __restrict__ beta) {
    int c = threadIdx.x;
    if (c >= 64) return;
    float S = 0.f, Q = 0.f;
    for (int i = 0; i < NSTATB; i++) {
        S += g_part[i * 128 + c];
        Q += g_part[i * 128 + 64 + c];
    }
    const float invM = 1.0f / (float)Mm;
    float mu  = S * invM;
    float var = Q * invM - mu * mu;
    float rs  = rsqrtf(var + EPSF);
    float sc  = gamma[c] * rs;
    g_scale[c] = sc;
    g_shift[c] = beta[c] - mu * sc;
}

__global__ __launch_bounds__(256) void apply_bn_kernel(int sel) {
    float* x = (sel == 1) ? g_f1 : g_f2;
    int i = blockIdx.x * blockDim.x + threadIdx.x;   // float4 index
    if (i >= (Mm * Cc) / 4) return;
    int c0 = (i & 15) * 4;
    float4 v = reinterpret_cast<float4*>(x)[i];
    v.x = fmaxf(0.f, v.x * g_scale[c0 + 0] + g_shift[c0 + 0]);
    v.y = fmaxf(0.f, v.y * g_scale[c0 + 1] + g_shift[c0 + 1]);
    v.z = fmaxf(0.f, v.z * g_scale[c0 + 2] + g_shift[c0 + 2]);
    v.w = fmaxf(0.f, v.w * g_scale[c0 + 3] + g_shift[c0 + 3]);
    reinterpret_cast<float4*>(x)[i] = v;
}

// ---------------- sampling + mean + proj + index emit --------------------------
__global__ __launch_bounds__(64) void sampler_kernel(const float* __restrict__ keypoints,
                                                     const float* __restrict__ query,
                                                     const float* __restrict__ projW,
                                                     const float* __restrict__ projb,
                                                     float* __restrict__ out,
                                                     int write_indices) {
    __shared__ int   s_sidx[Kk];
    __shared__ float s_fused[64];
    const int bn  = blockIdx.x;          // 0 .. B*N-1
    const int b   = bn / Nn;
    const int tid = threadIdx.x;

    if (tid < Kk) {
        const float* kp = keypoints + (bn * Kk + tid) * 3;
        int qx = (int)(kp[0] * 2.0f);
        int qy = (int)(kp[1] * 2.0f);
        int qz = (int)(kp[2] * 2.0f);
        qx = min(max(qx, 0), GX - 1);
        qy = min(max(qy, 0), GY - 1);
        qz = min(max(qz, 0), GZ - 1);
        int idx = g_grid[b * CELLS + (qx * GY + qy) * GZ + qz];
        s_sidx[tid] = idx < 0 ? 0 : idx;
        if (write_indices) {
            float* o = out + Bb * Nn * Cc + (bn * Kk + tid) * 4;
            o[0] = (float)b;
            o[1] = (float)qx;
            o[2] = (float)qy;
            o[3] = (float)qz;
        }
    }
    __syncthreads();
    float acc = 0.f;
    #pragma unroll
    for (int k = 0; k < Kk; k++) acc += g_f2[s_sidx[k] * 64 + tid];
    float fused = acc * (1.0f / (float)Kk) + query[bn * 64 + tid];
    s_fused[tid] = fused;
    __syncthreads();
    float o = projb[tid];
    const float* wr = projW + tid * 64;
    #pragma unroll
    for (int j = 0; j < 64; j++) o += s_fused[j] * wr[j];
    out[bn * 64 + tid] = o;
}

// ---------------- launch --------------------------------------------------------
extern "C" void kernel_launch(void* const* d_in, const int* in_sizes, int n_in,
                              void* d_out, int out_size) {
    const float* keypoints = (const float*)d_in[0];
    const float* query     = (const float*)d_in[1];
    const float* vfeat     = (const float*)d_in[2];
    const int*   vcoords   = (const int*)  d_in[3];
    const float* W1        = (const float*)d_in[4];
    const float* g1        = (const float*)d_in[5];
    const float* b1        = (const float*)d_in[6];
    const float* W2        = (const float*)d_in[7];
    const float* g2        = (const float*)d_in[8];
    const float* b2        = (const float*)d_in[9];
    const float* pW        = (const float*)d_in[10];
    const float* pb        = (const float*)d_in[11];
    float* out = (float*)d_out;

    init_grid_kernel<<<(Bb * CELLS + 255) / 256, 256>>>();
    scatter_kernel<<<(Mm + 255) / 256, 256>>>(vcoords);
    build_nbr_kernel<<<(Mm + 255) / 256, 256>>>(vcoords);

    conv_kernel<<<Mm / 64, 256>>>(vfeat, W1, 0, 1);
    stats_kernel<<<NSTATB, 256>>>(1);
    finalize_bn_kernel<<<1, 64>>>(g1, b1);
    apply_bn_kernel<<<(Mm * Cc / 4 + 255) / 256, 256>>>(1);

    conv_kernel<<<Mm / 64, 256>>>(vfeat, W2, 1, 2);
    stats_kernel<<<NSTATB, 256>>>(2);
    finalize_bn_kernel<<<1, 64>>>(g2, b2);
    apply_bn_kernel<<<(Mm * Cc / 4 + 255) / 256, 256>>>(2);

    int write_indices = (out_size >= Bb * Nn * Cc + Bb * Nn * Kk * 4) ? 1 : 0;
    sampler_kernel<<<Bb * Nn, 64>>>(keypoints, query, pW, pb, out, write_indices);
}

// round 6
// speedup vs baseline: 1.0111x; 1.0111x over previous
#include <cuda_runtime.h>
#include <cuda_bf16.h>

#define Bb 2
#define Vv 100000
#define Mm 200000          // B*V
#define Nn 8192
#define Kk 8
#define Cc 64
#define GX 128
#define GY 128
#define GZ 16
#define CELLS (GX*GY*GZ)   // 262144
#define EPSF 1e-5f
#define NSTATB 200
#define ROWS_PER_STATB (Mm / NSTATB)  // 1000

// ---------------- scratch (device globals; only referenced from device code) ---
__device__ int   g_grid[Bb * CELLS];          // 2 MB
__device__ int   g_nbr[Mm * 27];              // 21.6 MB
__device__ float g_f1[Mm * Cc];               // 51.2 MB
__device__ float g_f2[Mm * Cc];               // 51.2 MB
__device__ float g_part[NSTATB * 128];        // per-block [sum(64), sumsq(64)]
__device__ __align__(16) float g_scale[Cc];
__device__ __align__(16) float g_shift[Cc];

// ---------------- grid init / scatter / neighbor table ------------------------
__global__ void init_grid_kernel() {
    int i = blockIdx.x * blockDim.x + threadIdx.x;
    if (i < Bb * CELLS) g_grid[i] = -1;
}

__global__ void scatter_kernel(const int* __restrict__ coords) {
    int m = blockIdx.x * blockDim.x + threadIdx.x;
    if (m >= Mm) return;
    int b = m / Vv;
    int cx = coords[m * 3 + 0];
    int cy = coords[m * 3 + 1];
    int cz = coords[m * 3 + 2];
    g_grid[b * CELLS + (cx * GY + cy) * GZ + cz] = m;
}

__global__ void build_nbr_kernel(const int* __restrict__ coords) {
    int m = blockIdx.x * blockDim.x + threadIdx.x;
    if (m >= Mm) return;
    int b = m / Vv;
    int cx = coords[m * 3 + 0];
    int cy = coords[m * 3 + 1];
    int cz = coords[m * 3 + 2];
    const int* gb = g_grid + b * CELLS;
    int k = 0;
    #pragma unroll
    for (int dx = -1; dx <= 1; dx++)
      #pragma unroll
      for (int dy = -1; dy <= 1; dy++)
        #pragma unroll
        for (int dz = -1; dz <= 1; dz++) {
            int nx = cx + dx, ny = cy + dy, nz = cz + dz;
            int idx = -1;
            if (nx >= 0 && nx < GX && ny >= 0 && ny < GY && nz >= 0 && nz < GZ)
                idx = gb[(nx * GY + ny) * GZ + nz];
            g_nbr[m * 27 + k] = idx;
            k++;
        }
}

// ---------------- subm conv: 64-row tile, 27 offsets, smem GEMM ----------------
// blockDim = 256; each thread computes a 4x4 register tile of the 64x64 output.
// Inner loop j-blocked by 4: 8x LDS.128 per 64 FMA (was 5 LDS per 16 FMA).
// src_sel: 0 = ext (raw voxel features), 1 = g_f1 with fused BN1+ReLU on gather.
// dst_sel: 1 = g_f1, 2 = g_f2.
#define NF_STRIDE 68
__global__ __launch_bounds__(256) void conv_kernel(const float* __restrict__ ext,
                                                   const float* __restrict__ Wall,
                                                   int src_sel, int dst_sel) {
    __shared__ float s_W[64 * 64];
    __shared__ float s_nf[64 * NF_STRIDE];

    const float* feats = (src_sel == 0) ? ext : g_f1;
    float*       out   = (dst_sel == 1) ? g_f1 : g_f2;
    const bool   do_bn = (src_sel != 0);

    const int tid  = threadIdx.x;
    const int row0 = blockIdx.x * 64;
    const int tr   = tid >> 4;   // 0..15 -> output rows tr*4..tr*4+3
    const int tc   = tid & 15;   // 0..15 -> output cols tc*4..tc*4+3

    // fused BN params for the 4 channels this thread gathers (seg == tc)
    float4 bnsc = make_float4(1.f, 1.f, 1.f, 1.f);
    float4 bnsh = make_float4(0.f, 0.f, 0.f, 0.f);
    if (do_bn) {
        bnsc = *reinterpret_cast<const float4*>(&g_scale[tc * 4]);
        bnsh = *reinterpret_cast<const float4*>(&g_shift[tc * 4]);
    }

    float acc[4][4];
    #pragma unroll
    for (int i = 0; i < 4; i++)
        #pragma unroll
        for (int j = 0; j < 4; j++) acc[i][j] = 0.f;

    const float4* f4 = reinterpret_cast<const float4*>(feats);

    for (int k = 0; k < 27; k++) {
        // prefetch neighbor indices into registers (no smem, saves one sync)
        int idx[4];
        #pragma unroll
        for (int i = 0; i < 4; i++)
            idx[i] = g_nbr[(row0 + tr + 16 * i) * 27 + k];

        __syncthreads();   // previous compute done; safe to overwrite smem

        const float4* W4  = reinterpret_cast<const float4*>(Wall + k * 4096);
        float4*       sW4 = reinterpret_cast<float4*>(s_W);
        #pragma unroll
        for (int i = 0; i < 4; i++) sW4[tid + i * 256] = W4[tid + i * 256];

        #pragma unroll
        for (int i = 0; i < 4; i++) {
            int row = tr + 16 * i;
            float4 v = make_float4(0.f, 0.f, 0.f, 0.f);
            if (idx[i] >= 0) {
                v = f4[idx[i] * 16 + tc];
                if (do_bn) {
                    v.x = fmaxf(0.f, v.x * bnsc.x + bnsh.x);
                    v.y = fmaxf(0.f, v.y * bnsc.y + bnsh.y);
                    v.z = fmaxf(0.f, v.z * bnsc.z + bnsh.z);
                    v.w = fmaxf(0.f, v.w * bnsc.w + bnsh.w);
                }
            }
            *reinterpret_cast<float4*>(&s_nf[row * NF_STRIDE + tc * 4]) = v;
        }
        __syncthreads();   // tiles ready

        #pragma unroll 4
        for (int j = 0; j < 64; j += 4) {
            float4 b0 = *reinterpret_cast<const float4*>(&s_W[(j + 0) * 64 + tc * 4]);
            float4 b1 = *reinterpret_cast<const float4*>(&s_W[(j + 1) * 64 + tc * 4]);
            float4 b2 = *reinterpret_cast<const float4*>(&s_W[(j + 2) * 64 + tc * 4]);
            float4 b3 = *reinterpret_cast<const float4*>(&s_W[(j + 3) * 64 + tc * 4]);
            #pragma unroll
            for (int i = 0; i < 4; i++) {
                float4 a = *reinterpret_cast<const float4*>(&s_nf[(tr * 4 + i) * NF_STRIDE + j]);
                acc[i][0] = fmaf(a.x, b0.x, acc[i][0]);
                acc[i][1] = fmaf(a.x, b0.y, acc[i][1]);
                acc[i][2] = fmaf(a.x, b0.z, acc[i][2]);
                acc[i][3] = fmaf(a.x, b0.w, acc[i][3]);
                acc[i][0] = fmaf(a.y, b1.x, acc[i][0]);
                acc[i][1] = fmaf(a.y, b1.y, acc[i][1]);
                acc[i][2] = fmaf(a.y, b1.z, acc[i][2]);
                acc[i][3] = fmaf(a.y, b1.w, acc[i][3]);
                acc[i][0] = fmaf(a.z, b2.x, acc[i][0]);
                acc[i][1] = fmaf(a.z, b2.y, acc[i][1]);
                acc[i][2] = fmaf(a.z, b2.z, acc[i][2]);
                acc[i][3] = fmaf(a.z, b2.w, acc[i][3]);
                acc[i][0] = fmaf(a.w, b3.x, acc[i][0]);
                acc[i][1] = fmaf(a.w, b3.y, acc[i][1]);
                acc[i][2] = fmaf(a.w, b3.z, acc[i][2]);
                acc[i][3] = fmaf(a.w, b3.w, acc[i][3]);
            }
        }
    }
    #pragma unroll
    for (int i = 0; i < 4; i++) {
        float4 v = make_float4(acc[i][0], acc[i][1], acc[i][2], acc[i][3]);
        reinterpret_cast<float4*>(out)[((row0 + tr * 4 + i) * 64 + tc * 4) >> 2] = v;
    }
}

// ---------------- BN stats (deterministic 2-stage reduction) -------------------
__global__ __launch_bounds__(256) void stats_kernel(int sel) {
    __shared__ float ssum[256];
    __shared__ float ssq[256];
    const float* x = (sel == 1) ? g_f1 : g_f2;
    const int tid = threadIdx.x;
    const int c   = tid & 63;
    const int g   = tid >> 6;           // 0..3
    const int r0  = blockIdx.x * ROWS_PER_STATB;
    float s = 0.f, q = 0.f;
    for (int r = g; r < ROWS_PER_STATB; r += 4) {
        float v = x[(r0 + r) * 64 + c];
        s += v;
        q += v * v;
    }
    ssum[tid] = s; ssq[tid] = q;
    __syncthreads();
    if (g == 0) {
        float S = ssum[c] + ssum[64 + c] + ssum[128 + c] + ssum[192 + c];
        float Q = ssq[c]  + ssq[64 + c]  + ssq[128 + c]  + ssq[192 + c];
        g_part[blockIdx.x * 128 + c]      = S;
        g_part[blockIdx.x * 128 + 64 + c] = Q;
    }
}

__global__ void finalize_bn_kernel(const float* __restrict__ gamma,
                                   const float* __restrict__ beta) {
    int c = threadIdx.x;
    if (c >= 64) return;
    float S = 0.f, Q = 0.f;
    for (int i = 0; i < NSTATB; i++) {
        S += g_part[i * 128 + c];
        Q += g_part[i * 128 + 64 + c];
    }
    const float invM = 1.0f / (float)Mm;
    float mu  = S * invM;
    float var = Q * invM - mu * mu;
    float rs  = rsqrtf(var + EPSF);
    float sc  = gamma[c] * rs;
    g_scale[c] = sc;
    g_shift[c] = beta[c] - mu * sc;
}

// ---------------- sampling + fused BN2 + mean + proj + index emit --------------
__global__ __launch_bounds__(64) void sampler_kernel(const float* __restrict__ keypoints,
                                                     const float* __restrict__ query,
                                                     const float* __restrict__ projW,
                                                     const float* __restrict__ projb,
                                                     float* __restrict__ out,
                                                     int write_indices) {
    __shared__ int   s_sidx[Kk];
    __shared__ float s_fused[64];
    const int bn  = blockIdx.x;          // 0 .. B*N-1
    const int b   = bn / Nn;
    const int tid = threadIdx.x;

    if (tid < Kk) {
        const float* kp = keypoints + (bn * Kk + tid) * 3;
        int qx = (int)(kp[0] * 2.0f);
        int qy = (int)(kp[1] * 2.0f);
        int qz = (int)(kp[2] * 2.0f);
        qx = min(max(qx, 0), GX - 1);
        qy = min(max(qy, 0), GY - 1);
        qz = min(max(qz, 0), GZ - 1);
        int idx = g_grid[b * CELLS + (qx * GY + qy) * GZ + qz];
        s_sidx[tid] = idx < 0 ? 0 : idx;
        if (write_indices) {
            float* o = out + Bb * Nn * Cc + (bn * Kk + tid) * 4;
            o[0] = (float)b;
            o[1] = (float)qx;
            o[2] = (float)qy;
            o[3] = (float)qz;
        }
    }
    __syncthreads();
    const float sc = g_scale[tid];
    const float sh = g_shift[tid];
    float acc = 0.f;
    #pragma unroll
    for (int k = 0; k < Kk; k++) {
        float v = g_f2[s_sidx[k] * 64 + tid];
        acc += fmaxf(0.f, v * sc + sh);
    }
    float fused = acc * (1.0f / (float)Kk) + query[bn * 64 + tid];
    s_fused[tid] = fused;
    __syncthreads();
    float o = projb[tid];
    const float* wr = projW + tid * 64;
    #pragma unroll
    for (int j = 0; j < 64; j++) o += s_fused[j] * wr[j];
    out[bn * 64 + tid] = o;
}

// ---------------- launch --------------------------------------------------------
extern "C" void kernel_launch(void* const* d_in, const int* in_sizes, int n_in,
                              void* d_out, int out_size) {
    const float* keypoints = (const float*)d_in[0];
    const float* query     = (const float*)d_in[1];
    const float* vfeat     = (const float*)d_in[2];
    const int*   vcoords   = (const int*)  d_in[3];
    const float* W1        = (const float*)d_in[4];
    const float* g1        = (const float*)d_in[5];
    const float* b1        = (const float*)d_in[6];
    const float* W2        = (const float*)d_in[7];
    const float* g2        = (const float*)d_in[8];
    const float* b2        = (const float*)d_in[9];
    const float* pW        = (const float*)d_in[10];
    const float* pb        = (const float*)d_in[11];
    float* out = (float*)d_out;

    init_grid_kernel<<<(Bb * CELLS + 255) / 256, 256>>>();
    scatter_kernel<<<(Mm + 255) / 256, 256>>>(vcoords);
    build_nbr_kernel<<<(Mm + 255) / 256, 256>>>(vcoords);

    // conv1 (raw features) -> g_f1 (pre-BN)
    conv_kernel<<<Mm / 64, 256>>>(vfeat, W1, 0, 1);
    stats_kernel<<<NSTATB, 256>>>(1);
    finalize_bn_kernel<<<1, 64>>>(g1, b1);          // scale/shift = BN1

    // conv2 gathers g_f1 with fused BN1+ReLU -> g_f2 (pre-BN)
    conv_kernel<<<Mm / 64, 256>>>(vfeat, W2, 1, 2);
    stats_kernel<<<NSTATB, 256>>>(2);
    finalize_bn_kernel<<<1, 64>>>(g2, b2);          // scale/shift = BN2

    int write_indices = (out_size >= Bb * Nn * Cc + Bb * Nn * Kk * 4) ? 1 : 0;
    sampler_kernel<<<Bb * Nn, 64>>>(keypoints, query, pW, pb, out, write_indices);
}

// round 12
// speedup vs baseline: 2.2155x; 2.1911x over previous
#include <cuda_runtime.h>
#include <cuda_bf16.h>
#include <cstdint>

#define Bb 2
#define Vv 100000
#define Mm 200000          // B*V
#define Nn 8192
#define Kk 8
#define Cc 64
#define GX 128
#define GY 128
#define GZ 16
#define CELLS (GX*GY*GZ)
#define EPSF 1e-5f
#define NSTATB 200
#define ROWS_PER_STATB (Mm / NSTATB)
#define NT_TILES ((Mm + 127) / 128)   // 1563

// smem layout for conv (144B-padded rows; 144B = 36 banks -> conflict-free ldmatrix)
#define A_STRIDE 144
#define OFF_AHI 0
#define OFF_ALO 18432
#define OFF_WHI 36864
#define OFF_WLO 46080
#define CONV_SMEM 55296

// ---------------- scratch (device globals; only referenced from device code) ---
__device__ int   g_grid[Bb * CELLS];
__device__ int   g_nbr[Mm * 27];
__device__ float g_f1[Mm * Cc];
__device__ float g_f2[Mm * Cc];
__device__ float g_part[NSTATB * 128];
__device__ __align__(16) float g_scale[Cc];
__device__ __align__(16) float g_shift[Cc];
__device__ __align__(16) __nv_bfloat16 g_ahi[Mm * Cc];
__device__ __align__(16) __nv_bfloat16 g_alo[Mm * Cc];
__device__ __align__(16) __nv_bfloat16 g_wthi[27 * 64 * 64];   // [k][cout][cin]
__device__ __align__(16) __nv_bfloat16 g_wtlo[27 * 64 * 64];

__device__ __forceinline__ uint32_t smem_u32(const void* p) {
    uint32_t a;
    asm("{ .reg .u64 t; cvta.to.shared.u64 t, %1; cvt.u32.u64 %0, t; }" : "=r"(a) : "l"(p));
    return a;
}
#define LDSM_X4(r0, r1, r2, r3, addr) \
    asm volatile("ldmatrix.sync.aligned.m8n8.x4.shared.b16 {%0,%1,%2,%3}, [%4];" \
        : "=r"(r0), "=r"(r1), "=r"(r2), "=r"(r3) : "r"(addr))
#define MMA16816(d, a0, a1, a2, a3, b0, b1) \
    asm volatile("mma.sync.aligned.m16n8k16.row.col.f32.bf16.bf16.f32 " \
        "{%0,%1,%2,%3}, {%4,%5,%6,%7}, {%8,%9}, {%0,%1,%2,%3};" \
        : "+f"((d)[0]), "+f"((d)[1]), "+f"((d)[2]), "+f"((d)[3]) \
        : "r"(a0), "r"(a1), "r"(a2), "r"(a3), "r"(b0), "r"(b1))

// ---------------- grid init / scatter / neighbor table ------------------------
__global__ void init_grid_kernel() {
    int i = blockIdx.x * blockDim.x + threadIdx.x;
    if (i < Bb * CELLS) g_grid[i] = -1;
}

__global__ void scatter_kernel(const int* __restrict__ coords) {
    int m = blockIdx.x * blockDim.x + threadIdx.x;
    if (m >= Mm) return;
    int b = m / Vv;
    g_grid[b * CELLS + (coords[m*3] * GY + coords[m*3+1]) * GZ + coords[m*3+2]] = m;
}

__global__ void build_nbr_kernel(const int* __restrict__ coords) {
    int m = blockIdx.x * blockDim.x + threadIdx.x;
    if (m >= Mm) return;
    int b = m / Vv;
    int cx = coords[m*3], cy = coords[m*3+1], cz = coords[m*3+2];
    const int* gb = g_grid + b * CELLS;
    int k = 0;
    #pragma unroll
    for (int dx = -1; dx <= 1; dx++)
      #pragma unroll
      for (int dy = -1; dy <= 1; dy++)
        #pragma unroll
        for (int dz = -1; dz <= 1; dz++) {
            int nx = cx + dx, ny = cy + dy, nz = cz + dz;
            int idx = -1;
            if (nx >= 0 && nx < GX && ny >= 0 && ny < GY && nz >= 0 && nz < GZ)
                idx = gb[(nx * GY + ny) * GZ + nz];
            g_nbr[m * 27 + k] = idx;
            k++;
        }
}

// ---------------- weight prep: transpose + bf16 hi/lo split --------------------
__global__ void wprep_kernel(const float* __restrict__ W) {
    int i = blockIdx.x * blockDim.x + threadIdx.x;
    if (i >= 27 * 4096) return;
    int k = i >> 12, r = i & 4095;
    int n = r >> 6, kkk = r & 63;
    float x = W[k * 4096 + kkk * 64 + n];       // src [k][cin][cout]
    __nv_bfloat16 h = __float2bfloat16(x);
    __nv_bfloat16 l = __float2bfloat16(x - __bfloat162float(h));
    g_wthi[i] = h;                               // dst [k][cout][cin]
    g_wtlo[i] = l;
}

// ---------------- feature prep: (optional BN1+ReLU) + bf16 hi/lo split ---------
__global__ __launch_bounds__(256) void split_kernel(const float* __restrict__ ext, int mode) {
    int i4 = blockIdx.x * blockDim.x + threadIdx.x;   // float4 index
    if (i4 >= Mm * 16) return;
    const float4* s = (mode == 0) ? (const float4*)ext : (const float4*)g_f1;
    float4 v = s[i4];
    if (mode == 1) {
        int c0 = (i4 & 15) * 4;
        v.x = fmaxf(0.f, v.x * g_scale[c0+0] + g_shift[c0+0]);
        v.y = fmaxf(0.f, v.y * g_scale[c0+1] + g_shift[c0+1]);
        v.z = fmaxf(0.f, v.z * g_scale[c0+2] + g_shift[c0+2]);
        v.w = fmaxf(0.f, v.w * g_scale[c0+3] + g_shift[c0+3]);
    }
    __nv_bfloat16 h0 = __float2bfloat16(v.x), h1 = __float2bfloat16(v.y);
    __nv_bfloat16 h2 = __float2bfloat16(v.z), h3 = __float2bfloat16(v.w);
    __nv_bfloat16 l0 = __float2bfloat16(v.x - __bfloat162float(h0));
    __nv_bfloat16 l1 = __float2bfloat16(v.y - __bfloat162float(h1));
    __nv_bfloat16 l2 = __float2bfloat16(v.z - __bfloat162float(h2));
    __nv_bfloat16 l3 = __float2bfloat16(v.w - __bfloat162float(h3));
    __nv_bfloat162 ph0; ph0.x = h0; ph0.y = h1;
    __nv_bfloat162 ph1; ph1.x = h2; ph1.y = h3;
    __nv_bfloat162 pl0; pl0.x = l0; pl0.y = l1;
    __nv_bfloat162 pl1; pl1.x = l2; pl1.y = l3;
    uint2 uh, ul;
    uh.x = *reinterpret_cast<uint32_t*>(&ph0); uh.y = *reinterpret_cast<uint32_t*>(&ph1);
    ul.x = *reinterpret_cast<uint32_t*>(&pl0); ul.y = *reinterpret_cast<uint32_t*>(&pl1);
    reinterpret_cast<uint2*>(g_ahi)[i4] = uh;
    reinterpret_cast<uint2*>(g_alo)[i4] = ul;
}

// ---------------- HMMA conv: 128-row tile, 27 offsets --------------------------
// 8 warps; warp w owns rows w*16..w*16+15. hi/lo split, 3 products (skip lo*lo).
__global__ __launch_bounds__(256) void conv_mma_kernel(int dst_sel) {
    extern __shared__ char smem[];
    const int tid  = threadIdx.x;
    const int wid  = tid >> 5;
    const int lane = tid & 31;
    const int row0 = blockIdx.x * 128;
    float* out = (dst_sel == 1) ? g_f1 : g_f2;

    const uint32_t sb = smem_u32(smem);

    // per-lane ldmatrix address components
    const int row_in = lane & 7;
    const int aRow   = wid * 16 + ((lane >> 3) & 1) * 8 + row_in;  // local A row
    const int aColB  = (lane >> 4) * 16;                            // byte offset of k-sub
    const uint32_t aHiBase = sb + OFF_AHI + aRow * A_STRIDE + aColB;
    const uint32_t aLoBase = sb + OFF_ALO + aRow * A_STRIDE + aColB;
    const int nRow  = ((lane >> 4) & 1) * 8 + row_in;               // W row (n) within pair
    const int bColB = ((lane >> 3) & 1) * 16;                       // k-sub byte offset
    const uint32_t bHiBase = sb + OFF_WHI + nRow * A_STRIDE + bColB;
    const uint32_t bLoBase = sb + OFF_WLO + nRow * A_STRIDE + bColB;

    float acc[8][4];
    #pragma unroll
    for (int t = 0; t < 8; t++)
        #pragma unroll
        for (int j = 0; j < 4; j++) acc[t][j] = 0.f;

    for (int k = 0; k < 27; k++) {
        // prefetch neighbor indices (registers only; overlaps previous MMA tail)
        int idx[4];
        #pragma unroll
        for (int ss = 0; ss < 4; ss++) {
            int slot = tid + ss * 256;
            int rg   = row0 + (slot >> 3);
            idx[ss]  = (rg < Mm) ? g_nbr[rg * 27 + k] : -1;
        }
        __syncthreads();   // previous compute done
        // gather A rows (hi+lo)
        #pragma unroll
        for (int ss = 0; ss < 4; ss++) {
            int slot = tid + ss * 256;
            int row = slot >> 3, ch = slot & 7;
            uint4 vh = make_uint4(0, 0, 0, 0), vl = make_uint4(0, 0, 0, 0);
            if (idx[ss] >= 0) {
                vh = *reinterpret_cast<const uint4*>(&g_ahi[idx[ss] * 64 + ch * 8]);
                vl = *reinterpret_cast<const uint4*>(&g_alo[idx[ss] * 64 + ch * 8]);
            }
            *reinterpret_cast<uint4*>(smem + OFF_AHI + row * A_STRIDE + ch * 16) = vh;
            *reinterpret_cast<uint4*>(smem + OFF_ALO + row * A_STRIDE + ch * 16) = vl;
        }
        // W tiles (hi+lo)
        #pragma unroll
        for (int ss = 0; ss < 2; ss++) {
            int slot = tid + ss * 256;
            int n = slot >> 3, ch = slot & 7;
            uint4 wh = *reinterpret_cast<const uint4*>(&g_wthi[k * 4096 + n * 64 + ch * 8]);
            uint4 wl = *reinterpret_cast<const uint4*>(&g_wtlo[k * 4096 + n * 64 + ch * 8]);
            *reinterpret_cast<uint4*>(smem + OFF_WHI + n * A_STRIDE + ch * 16) = wh;
            *reinterpret_cast<uint4*>(smem + OFF_WLO + n * A_STRIDE + ch * 16) = wl;
        }
        __syncthreads();   // tiles ready

        #pragma unroll
        for (int c = 0; c < 4; c++) {        // k-chunks of 16
            uint32_t ah0, ah1, ah2, ah3, al0, al1, al2, al3;
            LDSM_X4(ah0, ah1, ah2, ah3, aHiBase + c * 32);
            LDSM_X4(al0, al1, al2, al3, aLoBase + c * 32);
            #pragma unroll
            for (int p = 0; p < 4; p++) {    // n-tile pairs
                uint32_t bh0, bh1, bh2, bh3, bl0, bl1, bl2, bl3;
                LDSM_X4(bh0, bh1, bh2, bh3, bHiBase + p * 16 * A_STRIDE + c * 32);
                LDSM_X4(bl0, bl1, bl2, bl3, bLoBase + p * 16 * A_STRIDE + c * 32);
                MMA16816(acc[2*p],     ah0, ah1, ah2, ah3, bh0, bh1);
                MMA16816(acc[2*p],     ah0, ah1, ah2, ah3, bl0, bl1);
                MMA16816(acc[2*p],     al0, al1, al2, al3, bh0, bh1);
                MMA16816(acc[2*p + 1], ah0, ah1, ah2, ah3, bh2, bh3);
                MMA16816(acc[2*p + 1], ah0, ah1, ah2, ah3, bl2, bl3);
                MMA16816(acc[2*p + 1], al0, al1, al2, al3, bh2, bh3);
            }
        }
    }

    // epilogue: D fragment -> gmem
    const int rA = row0 + wid * 16 + (lane >> 2);
    const int rB = rA + 8;
    const int c0 = (lane & 3) * 2;
    #pragma unroll
    for (int t = 0; t < 8; t++) {
        int col = t * 8 + c0;
        if (rA < Mm) *reinterpret_cast<float2*>(&out[rA * 64 + col]) = make_float2(acc[t][0], acc[t][1]);
        if (rB < Mm) *reinterpret_cast<float2*>(&out[rB * 64 + col]) = make_float2(acc[t][2], acc[t][3]);
    }
}

// ---------------- BN stats (deterministic 2-stage reduction) -------------------
__global__ __launch_bounds__(256) void stats_kernel(int sel) {
    __shared__ float ssum[256];
    __shared__ float ssq[256];
    const float* x = (sel == 1) ? g_f1 : g_f2;
    const int tid = threadIdx.x;
    const int c   = tid & 63;
    const int g   = tid >> 6;
    const int r0  = blockIdx.x * ROWS_PER_STATB;
    float s = 0.f, q = 0.f;
    for (int r = g; r < ROWS_PER_STATB; r += 4) {
        float v = x[(r0 + r) * 64 + c];
        s += v;
        q += v * v;
    }
    ssum[tid] = s; ssq[tid] = q;
    __syncthreads();
    if (g == 0) {
        float S = ssum[c] + ssum[64 + c] + ssum[128 + c] + ssum[192 + c];
        float Q = ssq[c]  + ssq[64 + c]  + ssq[128 + c]  + ssq[192 + c];
        g_part[blockIdx.x * 128 + c]      = S;
        g_part[blockIdx.x * 128 + 64 + c] = Q;
    }
}

__global__ void finalize_bn_kernel(const float* __restrict__ gamma,
                                   const float* __restrict__ beta) {
    int c = threadIdx.x;
    if (c >= 64) return;
    float S = 0.f, Q = 0.f;
    for (int i = 0; i < NSTATB; i++) {
        S += g_part[i * 128 + c];
        Q += g_part[i * 128 + 64 + c];
    }
    const float invM = 1.0f / (float)Mm;
    float mu  = S * invM;
    float var = Q * invM - mu * mu;
    float rs  = rsqrtf(var + EPSF);
    float sc  = gamma[c] * rs;
    g_scale[c] = sc;
    g_shift[c] = beta[c] - mu * sc;
}

// ---------------- sampling + fused BN2 + mean + proj + index emit --------------
__global__ __launch_bounds__(64) void sampler_kernel(const float* __restrict__ keypoints,
                                                     const float* __restrict__ query,
                                                     const float* __restrict__ projW,
                                                     const float* __restrict__ projb,
                                                     float* __restrict__ out,
                                                     int write_indices) {
    __shared__ int   s_sidx[Kk];
    __shared__ float s_fused[64];
    const int bn  = blockIdx.x;
    const int b   = bn / Nn;
    const int tid = threadIdx.x;

    if (tid < Kk) {
        const float* kp = keypoints + (bn * Kk + tid) * 3;
        int qx = (int)(kp[0] * 2.0f);
        int qy = (int)(kp[1] * 2.0f);
        int qz = (int)(kp[2] * 2.0f);
        qx = min(max(qx, 0), GX - 1);
        qy = min(max(qy, 0), GY - 1);
        qz = min(max(qz, 0), GZ - 1);
        int idx = g_grid[b * CELLS + (qx * GY + qy) * GZ + qz];
        s_sidx[tid] = idx < 0 ? 0 : idx;
        if (write_indices) {
            float* o = out + Bb * Nn * Cc + (bn * Kk + tid) * 4;
            o[0] = (float)b;
            o[1] = (float)qx;
            o[2] = (float)qy;
            o[3] = (float)qz;
        }
    }
    __syncthreads();
    const float sc = g_scale[tid];
    const float sh = g_shift[tid];
    float acc = 0.f;
    #pragma unroll
    for (int k = 0; k < Kk; k++) {
        float v = g_f2[s_sidx[k] * 64 + tid];
        acc += fmaxf(0.f, v * sc + sh);
    }
    float fused = acc * (1.0f / (float)Kk) + query[bn * 64 + tid];
    s_fused[tid] = fused;
    __syncthreads();
    float o = projb[tid];
    const float* wr = projW + tid * 64;
    #pragma unroll
    for (int j = 0; j < 64; j++) o += s_fused[j] * wr[j];
    out[bn * 64 + tid] = o;
}

// ---------------- launch --------------------------------------------------------
extern "C" void kernel_launch(void* const* d_in, const int* in_sizes, int n_in,
                              void* d_out, int out_size) {
    const float* keypoints = (const float*)d_in[0];
    const float* query     = (const float*)d_in[1];
    const float* vfeat     = (const float*)d_in[2];
    const int*   vcoords   = (const int*)  d_in[3];
    const float* W1        = (const float*)d_in[4];
    const float* g1        = (const float*)d_in[5];
    const float* b1        = (const float*)d_in[6];
    const float* W2        = (const float*)d_in[7];
    const float* g2        = (const float*)d_in[8];
    const float* b2        = (const float*)d_in[9];
    const float* pW        = (const float*)d_in[10];
    const float* pb        = (const float*)d_in[11];
    float* out = (float*)d_out;

    cudaFuncSetAttribute(conv_mma_kernel, cudaFuncAttributeMaxDynamicSharedMemorySize, CONV_SMEM);

    init_grid_kernel<<<(Bb * CELLS + 255) / 256, 256>>>();
    scatter_kernel<<<(Mm + 255) / 256, 256>>>(vcoords);
    build_nbr_kernel<<<(Mm + 255) / 256, 256>>>(vcoords);

    // conv1: split raw features + W1 -> HMMA conv -> g_f1 (pre-BN)
    wprep_kernel<<<(27 * 4096 + 255) / 256, 256>>>(W1);
    split_kernel<<<(Mm * 16 + 255) / 256, 256>>>(vfeat, 0);
    conv_mma_kernel<<<NT_TILES, 256, CONV_SMEM>>>(1);
    stats_kernel<<<NSTATB, 256>>>(1);
    finalize_bn_kernel<<<1, 64>>>(g1, b1);

    // conv2: split BN1(g_f1)+ReLU + W2 -> HMMA conv -> g_f2 (pre-BN)
    wprep_kernel<<<(27 * 4096 + 255) / 256, 256>>>(W2);
    split_kernel<<<(Mm * 16 + 255) / 256, 256>>>(vfeat, 1);
    conv_mma_kernel<<<NT_TILES, 256, CONV_SMEM>>>(2);
    stats_kernel<<<NSTATB, 256>>>(2);
    finalize_bn_kernel<<<1, 64>>>(g2, b2);

    int write_indices = (out_size >= Bb * Nn * Cc + Bb * Nn * Kk * 4) ? 1 : 0;
    sampler_kernel<<<Bb * Nn, 64>>>(keypoints, query, pW, pb, out, write_indices);
}

// round 14
// speedup vs baseline: 2.3065x; 1.0411x over previous
#include <cuda_runtime.h>
#include <cuda_bf16.h>
#include <cstdint>

#define Bb 2
#define Vv 100000
#define Mm 200000          // B*V
#define Nn 8192
#define Kk 8
#define Cc 64
#define GX 128
#define GY 128
#define GZ 16
#define CELLS (GX*GY*GZ)
#define EPSF 1e-5f
#define NSTATB 200
#define ROWS_PER_STATB (Mm / NSTATB)
#define NT_TILES ((Mm + 127) / 128)   // 1563

// smem stage layout (144B-padded rows; 144B = 36 banks -> conflict-free ldmatrix)
#define A_STRIDE 144
#define OFF_AHI 0
#define OFF_ALO 18432
#define OFF_WHI 36864
#define OFF_WLO 46080
#define STAGE_BYTES 55296
#define CONV_SMEM (2 * STAGE_BYTES)   // 110592

// ---------------- scratch (device globals; only referenced from device code) ---
__device__ int   g_grid[Bb * CELLS];
__device__ int   g_nbr[Mm * 27];
__device__ float g_f1[Mm * Cc];
__device__ float g_f2[Mm * Cc];
__device__ float g_part[NSTATB * 128];
__device__ __align__(16) float g_scale[Cc];
__device__ __align__(16) float g_shift[Cc];
__device__ __align__(16) __nv_bfloat16 g_ahi[Mm * Cc];
__device__ __align__(16) __nv_bfloat16 g_alo[Mm * Cc];
__device__ __align__(16) __nv_bfloat16 g_wthi[27 * 64 * 64];   // [k][cout][cin]
__device__ __align__(16) __nv_bfloat16 g_wtlo[27 * 64 * 64];

__device__ __forceinline__ uint32_t smem_u32(const void* p) {
    uint32_t a;
    asm("{ .reg .u64 t; cvta.to.shared.u64 t, %1; cvt.u32.u64 %0, t; }" : "=r"(a) : "l"(p));
    return a;
}
#define LDSM_X4(r0, r1, r2, r3, addr) \
    asm volatile("ldmatrix.sync.aligned.m8n8.x4.shared.b16 {%0,%1,%2,%3}, [%4];" \
        : "=r"(r0), "=r"(r1), "=r"(r2), "=r"(r3) : "r"(addr))
// NOTE: non-volatile — pure register op, lets ptxas schedule/interleave MMAs
#define MMA16816(d, a0, a1, a2, a3, b0, b1) \
    asm("mma.sync.aligned.m16n8k16.row.col.f32.bf16.bf16.f32 " \
        "{%0,%1,%2,%3}, {%4,%5,%6,%7}, {%8,%9}, {%0,%1,%2,%3};" \
        : "+f"((d)[0]), "+f"((d)[1]), "+f"((d)[2]), "+f"((d)[3]) \
        : "r"(a0), "r"(a1), "r"(a2), "r"(a3), "r"(b0), "r"(b1))
// 16B cp.async; src_size (0 or 16) zero-fills when 0 — free zero-padding
#define CP_ASYNC16(smem, gptr, sz) \
    asm volatile("cp.async.cg.shared.global [%0], [%1], 16, %2;" \
        :: "r"((uint32_t)(smem)), "l"(gptr), "r"((uint32_t)(sz)) : "memory")
#define CP_COMMIT() asm volatile("cp.async.commit_group;" ::: "memory")
#define CP_WAIT(n)  asm volatile("cp.async.wait_group %0;" :: "n"(n) : "memory")

// ---------------- grid init / scatter / neighbor table ------------------------
__global__ void init_grid_kernel() {
    int i = blockIdx.x * blockDim.x + threadIdx.x;
    if (i < Bb * CELLS) g_grid[i] = -1;
}

__global__ void scatter_kernel(const int* __restrict__ coords) {
    int m = blockIdx.x * blockDim.x + threadIdx.x;
    if (m >= Mm) return;
    int b = m / Vv;
    g_grid[b * CELLS + (coords[m*3] * GY + coords[m*3+1]) * GZ + coords[m*3+2]] = m;
}

__global__ void build_nbr_kernel(const int* __restrict__ coords) {
    int m = blockIdx.x * blockDim.x + threadIdx.x;
    if (m >= Mm) return;
    int b = m / Vv;
    int cx = coords[m*3], cy = coords[m*3+1], cz = coords[m*3+2];
    const int* gb = g_grid + b * CELLS;
    int k = 0;
    #pragma unroll
    for (int dx = -1; dx <= 1; dx++)
      #pragma unroll
      for (int dy = -1; dy <= 1; dy++)
        #pragma unroll
        for (int dz = -1; dz <= 1; dz++) {
            int nx = cx + dx, ny = cy + dy, nz = cz + dz;
            int idx = -1;
            if (nx >= 0 && nx < GX && ny >= 0 && ny < GY && nz >= 0 && nz < GZ)
                idx = gb[(nx * GY + ny) * GZ + nz];
            g_nbr[m * 27 + k] = idx;
            k++;
        }
}

// ---------------- weight prep: transpose + bf16 hi/lo split --------------------
__global__ void wprep_kernel(const float* __restrict__ W) {
    int i = blockIdx.x * blockDim.x + threadIdx.x;
    if (i >= 27 * 4096) return;
    int k = i >> 12, r = i & 4095;
    int n = r >> 6, kkk = r & 63;
    float x = W[k * 4096 + kkk * 64 + n];       // src [k][cin][cout]
    __nv_bfloat16 h = __float2bfloat16(x);
    __nv_bfloat16 l = __float2bfloat16(x - __bfloat162float(h));
    g_wthi[i] = h;                               // dst [k][cout][cin]
    g_wtlo[i] = l;
}

// ---------------- feature prep: (optional BN1+ReLU) + bf16 hi/lo split ---------
__global__ __launch_bounds__(256) void split_kernel(const float* __restrict__ ext, int mode) {
    int i4 = blockIdx.x * blockDim.x + threadIdx.x;   // float4 index
    if (i4 >= Mm * 16) return;
    const float4* s = (mode == 0) ? (const float4*)ext : (const float4*)g_f1;
    float4 v = s[i4];
    if (mode == 1) {
        int c0 = (i4 & 15) * 4;
        v.x = fmaxf(0.f, v.x * g_scale[c0+0] + g_shift[c0+0]);
        v.y = fmaxf(0.f, v.y * g_scale[c0+1] + g_shift[c0+1]);
        v.z = fmaxf(0.f, v.z * g_scale[c0+2] + g_shift[c0+2]);
        v.w = fmaxf(0.f, v.w * g_scale[c0+3] + g_shift[c0+3]);
    }
    __nv_bfloat16 h0 = __float2bfloat16(v.x), h1 = __float2bfloat16(v.y);
    __nv_bfloat16 h2 = __float2bfloat16(v.z), h3 = __float2bfloat16(v.w);
    __nv_bfloat16 l0 = __float2bfloat16(v.x - __bfloat162float(h0));
    __nv_bfloat16 l1 = __float2bfloat16(v.y - __bfloat162float(h1));
    __nv_bfloat16 l2 = __float2bfloat16(v.z - __bfloat162float(h2));
    __nv_bfloat16 l3 = __float2bfloat16(v.w - __bfloat162float(h3));
    __nv_bfloat162 ph0; ph0.x = h0; ph0.y = h1;
    __nv_bfloat162 ph1; ph1.x = h2; ph1.y = h3;
    __nv_bfloat162 pl0; pl0.x = l0; pl0.y = l1;
    __nv_bfloat162 pl1; pl1.x = l2; pl1.y = l3;
    uint2 uh, ul;
    uh.x = *reinterpret_cast<uint32_t*>(&ph0); uh.y = *reinterpret_cast<uint32_t*>(&ph1);
    ul.x = *reinterpret_cast<uint32_t*>(&pl0); ul.y = *reinterpret_cast<uint32_t*>(&pl1);
    reinterpret_cast<uint2*>(g_ahi)[i4] = uh;
    reinterpret_cast<uint2*>(g_alo)[i4] = ul;
}

// ---------------- HMMA conv: 128-row tile, 27 offsets, cp.async double-buffer --
__global__ __launch_bounds__(256) void conv_mma_kernel(int dst_sel) {
    extern __shared__ char smem[];
    const int tid  = threadIdx.x;
    const int wid  = tid >> 5;
    const int lane = tid & 31;
    const int row0 = blockIdx.x * 128;
    float* out = (dst_sel == 1) ? g_f1 : g_f2;

    const uint32_t sb = smem_u32(smem);

    // per-thread copy slots: 4 A-slots (row, chunk) + 2 W-slots
    const int aSlotRow[4] = { (tid + 0)   >> 3, (tid + 256) >> 3, (tid + 512) >> 3, (tid + 768) >> 3 };
    const int aSlotCh     = tid & 7;
    const int wSlotN[2]   = { (tid + 0) >> 3, (tid + 256) >> 3 };

    // per-lane ldmatrix address components
    const int row_in = lane & 7;
    const int aRow   = wid * 16 + ((lane >> 3) & 1) * 8 + row_in;
    const int aColB  = (lane >> 4) * 16;
    const int nRow   = ((lane >> 4) & 1) * 8 + row_in;
    const int bColB  = ((lane >> 3) & 1) * 16;

    float acc[8][4];
    #pragma unroll
    for (int t = 0; t < 8; t++)
        #pragma unroll
        for (int j = 0; j < 4; j++) acc[t][j] = 0.f;

    // issue cp.async for offset k into stage s
    auto issue_stage = [&](int k, int s) {
        char* st = smem + s * STAGE_BYTES;
        #pragma unroll
        for (int ss = 0; ss < 4; ss++) {
            int row = aSlotRow[ss];
            int rg  = row0 + row;
            int idx = (rg < Mm) ? g_nbr[rg * 27 + k] : -1;
            uint32_t sz = (idx >= 0) ? 16u : 0u;
            long off = (idx >= 0) ? (long)idx * 64 + aSlotCh * 8 : 0;
            uint32_t dst = sb + (uint32_t)(s * STAGE_BYTES) + (uint32_t)(row * A_STRIDE + aSlotCh * 16);
            CP_ASYNC16(dst + OFF_AHI, (const char*)&g_ahi[off], sz);
            CP_ASYNC16(dst + OFF_ALO, (const char*)&g_alo[off], sz);
        }
        #pragma unroll
        for (int ss = 0; ss < 2; ss++) {
            int n = wSlotN[ss];
            uint32_t dst = sb + (uint32_t)(s * STAGE_BYTES) + (uint32_t)(n * A_STRIDE + aSlotCh * 16);
            const char* srcH = (const char*)&g_wthi[k * 4096 + n * 64 + aSlotCh * 8];
            const char* srcL = (const char*)&g_wtlo[k * 4096 + n * 64 + aSlotCh * 8];
            CP_ASYNC16(dst + OFF_WHI, srcH, 16u);
            CP_ASYNC16(dst + OFF_WLO, srcL, 16u);
        }
        CP_COMMIT();
    };

    issue_stage(0, 0);

    for (int k = 0; k < 27; k++) {
        const int s = k & 1;
        if (k + 1 < 27) {
            __syncthreads();            // all warps done MMA(k-1) on stage s^1
            issue_stage(k + 1, s ^ 1);
            CP_WAIT(1);                 // stage s (group issued last iter) done
        } else {
            CP_WAIT(0);
        }
        __syncthreads();                // everyone's copies for stage s landed

        const uint32_t stb    = sb + (uint32_t)(s * STAGE_BYTES);
        const uint32_t aHiB   = stb + OFF_AHI + aRow * A_STRIDE + aColB;
        const uint32_t aLoB   = stb + OFF_ALO + aRow * A_STRIDE + aColB;
        const uint32_t bHiB   = stb + OFF_WHI + nRow * A_STRIDE + bColB;
        const uint32_t bLoB   = stb + OFF_WLO + nRow * A_STRIDE + bColB;

        #pragma unroll
        for (int c = 0; c < 4; c++) {        // k-chunks of 16
            uint32_t ah0, ah1, ah2, ah3, al0, al1, al2, al3;
            LDSM_X4(ah0, ah1, ah2, ah3, aHiB + c * 32);
            LDSM_X4(al0, al1, al2, al3, aLoB + c * 32);
            #pragma unroll
            for (int p = 0; p < 4; p++) {    // n-tile pairs
                uint32_t bh0, bh1, bh2, bh3, bl0, bl1, bl2, bl3;
                LDSM_X4(bh0, bh1, bh2, bh3, bHiB + p * 16 * A_STRIDE + c * 32);
                LDSM_X4(bl0, bl1, bl2, bl3, bLoB + p * 16 * A_STRIDE + c * 32);
                // alternate accumulators to break RAW chains
                MMA16816(acc[2*p],     ah0, ah1, ah2, ah3, bh0, bh1);
                MMA16816(acc[2*p + 1], ah0, ah1, ah2, ah3, bh2, bh3);
                MMA16816(acc[2*p],     ah0, ah1, ah2, ah3, bl0, bl1);
                MMA16816(acc[2*p + 1], ah0, ah1, ah2, ah3, bl2, bl3);
                MMA16816(acc[2*p],     al0, al1, al2, al3, bh0, bh1);
                MMA16816(acc[2*p + 1], al0, al1, al2, al3, bh2, bh3);
            }
        }
    }

    // epilogue: D fragment -> gmem
    const int rA = row0 + wid * 16 + (lane >> 2);
    const int rB = rA + 8;
    const int c0 = (lane & 3) * 2;
    #pragma unroll
    for (int t = 0; t < 8; t++) {
        int col = t * 8 + c0;
        if (rA < Mm) *reinterpret_cast<float2*>(&out[rA * 64 + col]) = make_float2(acc[t][0], acc[t][1]);
        if (rB < Mm) *reinterpret_cast<float2*>(&out[rB * 64 + col]) = make_float2(acc[t][2], acc[t][3]);
    }
}

// ---------------- BN stats (deterministic 2-stage reduction) -------------------
__global__ __launch_bounds__(256) void stats_kernel(int sel) {
    __shared__ float ssum[256];
    __shared__ float ssq[256];
    const float* x = (sel == 1) ? g_f1 : g_f2;
    const int tid = threadIdx.x;
    const int c   = tid & 63;
    const int g   = tid >> 6;
    const int r0  = blockIdx.x * ROWS_PER_STATB;
    float s = 0.f, q = 0.f;
    for (int r = g; r < ROWS_PER_STATB; r += 4) {
        float v = x[(r0 + r) * 64 + c];
        s += v;
        q += v * v;
    }
    ssum[tid] = s; ssq[tid] = q;
    __syncthreads();
    if (g == 0) {
        float S = ssum[c] + ssum[64 + c] + ssum[128 + c] + ssum[192 + c];
        float Q = ssq[c]  + ssq[64 + c]  + ssq[128 + c]  + ssq[192 + c];
        g_part[blockIdx.x * 128 + c]      = S;
        g_part[blockIdx.x * 128 + 64 + c] = Q;
    }
}

__global__ void finalize_bn_kernel(const float* __restrict__ gamma,
                                   const float* __restrict__ beta) {
    int c = threadIdx.x;
    if (c >= 64) return;
    float S = 0.f, Q = 0.f;
    for (int i = 0; i < NSTATB; i++) {
        S += g_part[i * 128 + c];
        Q += g_part[i * 128 + 64 + c];
    }
    const float invM = 1.0f / (float)Mm;
    float mu  = S * invM;
    float var = Q * invM - mu * mu;
    float rs  = rsqrtf(var + EPSF);
    float sc  = gamma[c] * rs;
    g_scale[c] = sc;
    g_shift[c] = beta[c] - mu * sc;
}

// ---------------- sampling + fused BN2 + mean + proj + index emit --------------
__global__ __launch_bounds__(64) void sampler_kernel(const float* __restrict__ keypoints,
                                                     const float* __restrict__ query,
                                                     const float* __restrict__ projW,
                                                     const float* __restrict__ projb,
                                                     float* __restrict__ out,
                                                     int write_indices) {
    __shared__ int   s_sidx[Kk];
    __shared__ float s_fused[64];
    const int bn  = blockIdx.x;
    const int b   = bn / Nn;
    const int tid = threadIdx.x;

    if (tid < Kk) {
        const float* kp = keypoints + (bn * Kk + tid) * 3;
        int qx = (int)(kp[0] * 2.0f);
        int qy = (int)(kp[1] * 2.0f);
        int qz = (int)(kp[2] * 2.0f);
        qx = min(max(qx, 0), GX - 1);
        qy = min(max(qy, 0), GY - 1);
        qz = min(max(qz, 0), GZ - 1);
        int idx = g_grid[b * CELLS + (qx * GY + qy) * GZ + qz];
        s_sidx[tid] = idx < 0 ? 0 : idx;
        if (write_indices) {
            float* o = out + Bb * Nn * Cc + (bn * Kk + tid) * 4;
            o[0] = (float)b;
            o[1] = (float)qx;
            o[2] = (float)qy;
            o[3] = (float)qz;
        }
    }
    __syncthreads();
    const float sc = g_scale[tid];
    const float sh = g_shift[tid];
    float acc = 0.f;
    #pragma unroll
    for (int k = 0; k < Kk; k++) {
        float v = g_f2[s_sidx[k] * 64 + tid];
        acc += fmaxf(0.f, v * sc + sh);
    }
    float fused = acc * (1.0f / (float)Kk) + query[bn * 64 + tid];
    s_fused[tid] = fused;
    __syncthreads();
    float o = projb[tid];
    const float* wr = projW + tid * 64;
    #pragma unroll
    for (int j = 0; j < 64; j++) o += s_fused[j] * wr[j];
    out[bn * 64 + tid] = o;
}

// ---------------- launch --------------------------------------------------------
extern "C" void kernel_launch(void* const* d_in, const int* in_sizes, int n_in,
                              void* d_out, int out_size) {
    const float* keypoints = (const float*)d_in[0];
    const float* query     = (const float*)d_in[1];
    const float* vfeat     = (const float*)d_in[2];
    const int*   vcoords   = (const int*)  d_in[3];
    const float* W1        = (const float*)d_in[4];
    const float* g1        = (const float*)d_in[5];
    const float* b1        = (const float*)d_in[6];
    const float* W2        = (const float*)d_in[7];
    const float* g2        = (const float*)d_in[8];
    const float* b2        = (const float*)d_in[9];
    const float* pW        = (const float*)d_in[10];
    const float* pb        = (const float*)d_in[11];
    float* out = (float*)d_out;

    cudaFuncSetAttribute(conv_mma_kernel, cudaFuncAttributeMaxDynamicSharedMemorySize, CONV_SMEM);

    init_grid_kernel<<<(Bb * CELLS + 255) / 256, 256>>>();
    scatter_kernel<<<(Mm + 255) / 256, 256>>>(vcoords);
    build_nbr_kernel<<<(Mm + 255) / 256, 256>>>(vcoords);

    // conv1: split raw features + W1 -> HMMA conv -> g_f1 (pre-BN)
    wprep_kernel<<<(27 * 4096 + 255) / 256, 256>>>(W1);
    split_kernel<<<(Mm * 16 + 255) / 256, 256>>>(vfeat, 0);
    conv_mma_kernel<<<NT_TILES, 256, CONV_SMEM>>>(1);
    stats_kernel<<<NSTATB, 256>>>(1);
    finalize_bn_kernel<<<1, 64>>>(g1, b1);

    // conv2: split BN1(g_f1)+ReLU + W2 -> HMMA conv -> g_f2 (pre-BN)
    wprep_kernel<<<(27 * 4096 + 255) / 256, 256>>>(W2);
    split_kernel<<<(Mm * 16 + 255) / 256, 256>>>(vfeat, 1);
    conv_mma_kernel<<<NT_TILES, 256, CONV_SMEM>>>(2);
    stats_kernel<<<NSTATB, 256>>>(2);
    finalize_bn_kernel<<<1, 64>>>(g2, b2);

    int write_indices = (out_size >= Bb * Nn * Cc + Bb * Nn * Kk * 4) ? 1 : 0;
    sampler_kernel<<<Bb * Nn, 64>>>(keypoints, query, pW, pb, out, write_indices);
}

// round 15
// speedup vs baseline: 3.6375x; 1.5771x over previous
#include <cuda_runtime.h>
#include <cuda_fp16.h>
#include <cstdint>

#define Bb 2
#define Vv 100000
#define Mm 200000          // B*V
#define Nn 8192
#define Kk 8
#define Cc 64
#define GX 128
#define GY 128
#define GZ 16
#define CELLS (GX*GY*GZ)
#define EPSF 1e-5f
#define NSTATB 200
#define ROWS_PER_STATB (Mm / NSTATB)
#define NT_TILES ((Mm + 127) / 128)   // 1563

// smem stage layout (144B-padded rows; 144B = 36 banks -> conflict-free ldmatrix)
#define A_STRIDE 144
#define OFF_A 0
#define OFF_W 18432                   // 128 rows * 144B
#define STAGE_BYTES 27648             // + 64 rows * 144B
#define CONV_SMEM (2 * STAGE_BYTES)   // 55296

// ---------------- scratch (device globals; only referenced from device code) ---
__device__ int   g_grid[Bb * CELLS];
__device__ int   g_nbr[Mm * 27];
__device__ float g_f1[Mm * Cc];
__device__ float g_f2[Mm * Cc];
__device__ float g_part[NSTATB * 128];
__device__ __align__(16) float g_scale[Cc];
__device__ __align__(16) float g_shift[Cc];
__device__ __align__(16) __half g_a16[Mm * Cc];          // 25.6 MB (fp16 features)
__device__ __align__(16) __half g_wt16[27 * 64 * 64];    // [k][cout][cin] fp16

__device__ __forceinline__ uint32_t smem_u32(const void* p) {
    uint32_t a;
    asm("{ .reg .u64 t; cvta.to.shared.u64 t, %1; cvt.u32.u64 %0, t; }" : "=r"(a) : "l"(p));
    return a;
}
#define LDSM_X4(r0, r1, r2, r3, addr) \
    asm volatile("ldmatrix.sync.aligned.m8n8.x4.shared.b16 {%0,%1,%2,%3}, [%4];" \
        : "=r"(r0), "=r"(r1), "=r"(r2), "=r"(r3) : "r"(addr))
// fp16 inputs, fp32 accumulate; non-volatile so ptxas can schedule freely
#define MMA16816(d, a0, a1, a2, a3, b0, b1) \
    asm("mma.sync.aligned.m16n8k16.row.col.f32.f16.f16.f32 " \
        "{%0,%1,%2,%3}, {%4,%5,%6,%7}, {%8,%9}, {%0,%1,%2,%3};" \
        : "+f"((d)[0]), "+f"((d)[1]), "+f"((d)[2]), "+f"((d)[3]) \
        : "r"(a0), "r"(a1), "r"(a2), "r"(a3), "r"(b0), "r"(b1))
// 16B cp.async; src_size (0 or 16) zero-fills when 0 — free zero-padding
#define CP_ASYNC16(smem, gptr, sz) \
    asm volatile("cp.async.cg.shared.global [%0], [%1], 16, %2;" \
        :: "r"((uint32_t)(smem)), "l"(gptr), "r"((uint32_t)(sz)) : "memory")
#define CP_COMMIT() asm volatile("cp.async.commit_group;" ::: "memory")
#define CP_WAIT(n)  asm volatile("cp.async.wait_group %0;" :: "n"(n) : "memory")

// ---------------- grid init / scatter / neighbor table ------------------------
__global__ void init_grid_kernel() {
    int i = blockIdx.x * blockDim.x + threadIdx.x;
    if (i < Bb * CELLS) g_grid[i] = -1;
}

__global__ void scatter_kernel(const int* __restrict__ coords) {
    int m = blockIdx.x * blockDim.x + threadIdx.x;
    if (m >= Mm) return;
    int b = m / Vv;
    g_grid[b * CELLS + (coords[m*3] * GY + coords[m*3+1]) * GZ + coords[m*3+2]] = m;
}

__global__ void build_nbr_kernel(const int* __restrict__ coords) {
    int m = blockIdx.x * blockDim.x + threadIdx.x;
    if (m >= Mm) return;
    int b = m / Vv;
    int cx = coords[m*3], cy = coords[m*3+1], cz = coords[m*3+2];
    const int* gb = g_grid + b * CELLS;
    int k = 0;
    #pragma unroll
    for (int dx = -1; dx <= 1; dx++)
      #pragma unroll
      for (int dy = -1; dy <= 1; dy++)
        #pragma unroll
        for (int dz = -1; dz <= 1; dz++) {
            int nx = cx + dx, ny = cy + dy, nz = cz + dz;
            int idx = -1;
            if (nx >= 0 && nx < GX && ny >= 0 && ny < GY && nz >= 0 && nz < GZ)
                idx = gb[(nx * GY + ny) * GZ + nz];
            g_nbr[m * 27 + k] = idx;
            k++;
        }
}

// ---------------- weight prep: transpose + fp16 convert ------------------------
__global__ void wprep_kernel(const float* __restrict__ W) {
    int i = blockIdx.x * blockDim.x + threadIdx.x;
    if (i >= 27 * 4096) return;
    int k = i >> 12, r = i & 4095;
    int n = r >> 6, kkk = r & 63;
    g_wt16[i] = __float2half(W[k * 4096 + kkk * 64 + n]);   // [k][cin][cout] -> [k][cout][cin]
}

// ---------------- feature prep: (optional BN1+ReLU) + fp16 convert -------------
__global__ __launch_bounds__(256) void split_kernel(const float* __restrict__ ext, int mode) {
    int i4 = blockIdx.x * blockDim.x + threadIdx.x;   // float4 index
    if (i4 >= Mm * 16) return;
    const float4* s = (mode == 0) ? (const float4*)ext : (const float4*)g_f1;
    float4 v = s[i4];
    if (mode == 1) {
        int c0 = (i4 & 15) * 4;
        v.x = fmaxf(0.f, v.x * g_scale[c0+0] + g_shift[c0+0]);
        v.y = fmaxf(0.f, v.y * g_scale[c0+1] + g_shift[c0+1]);
        v.z = fmaxf(0.f, v.z * g_scale[c0+2] + g_shift[c0+2]);
        v.w = fmaxf(0.f, v.w * g_scale[c0+3] + g_shift[c0+3]);
    }
    __half2 p0 = __halves2half2(__float2half(v.x), __float2half(v.y));
    __half2 p1 = __halves2half2(__float2half(v.z), __float2half(v.w));
    uint2 u;
    u.x = *reinterpret_cast<uint32_t*>(&p0);
    u.y = *reinterpret_cast<uint32_t*>(&p1);
    reinterpret_cast<uint2*>(g_a16)[i4] = u;
}

// ---------------- HMMA conv: 128-row tile, 27 offsets, cp.async double-buffer --
__global__ __launch_bounds__(256) void conv_mma_kernel(int dst_sel) {
    extern __shared__ char smem[];
    const int tid  = threadIdx.x;
    const int wid  = tid >> 5;
    const int lane = tid & 31;
    const int row0 = blockIdx.x * 128;
    float* out = (dst_sel == 1) ? g_f1 : g_f2;

    const uint32_t sb = smem_u32(smem);

    // per-thread copy slots: 4 A-slots (row, chunk) + 2 W-slots
    const int aSlotRow[4] = { (tid + 0)   >> 3, (tid + 256) >> 3, (tid + 512) >> 3, (tid + 768) >> 3 };
    const int aSlotCh     = tid & 7;
    const int wSlotN[2]   = { (tid + 0) >> 3, (tid + 256) >> 3 };

    // per-lane ldmatrix address components
    const int row_in = lane & 7;
    const int aRow   = wid * 16 + ((lane >> 3) & 1) * 8 + row_in;
    const int aColB  = (lane >> 4) * 16;
    const int nRow   = ((lane >> 4) & 1) * 8 + row_in;
    const int bColB  = ((lane >> 3) & 1) * 16;

    float acc[8][4];
    #pragma unroll
    for (int t = 0; t < 8; t++)
        #pragma unroll
        for (int j = 0; j < 4; j++) acc[t][j] = 0.f;

    // issue cp.async for offset k into stage s
    auto issue_stage = [&](int k, int s) {
        #pragma unroll
        for (int ss = 0; ss < 4; ss++) {
            int row = aSlotRow[ss];
            int rg  = row0 + row;
            int idx = (rg < Mm) ? g_nbr[rg * 27 + k] : -1;
            uint32_t sz = (idx >= 0) ? 16u : 0u;
            long off = (idx >= 0) ? (long)idx * 64 + aSlotCh * 8 : 0;
            uint32_t dst = sb + (uint32_t)(s * STAGE_BYTES) + (uint32_t)(row * A_STRIDE + aSlotCh * 16);
            CP_ASYNC16(dst + OFF_A, (const char*)&g_a16[off], sz);
        }
        #pragma unroll
        for (int ss = 0; ss < 2; ss++) {
            int n = wSlotN[ss];
            uint32_t dst = sb + (uint32_t)(s * STAGE_BYTES) + (uint32_t)(n * A_STRIDE + aSlotCh * 16);
            CP_ASYNC16(dst + OFF_W, (const char*)&g_wt16[k * 4096 + n * 64 + aSlotCh * 8], 16u);
        }
        CP_COMMIT();
    };

    issue_stage(0, 0);

    for (int k = 0; k < 27; k++) {
        const int s = k & 1;
        if (k + 1 < 27) {
            __syncthreads();            // all warps done MMA(k-1) on stage s^1
            issue_stage(k + 1, s ^ 1);
            CP_WAIT(1);                 // stage s (group issued last iter) done
        } else {
            CP_WAIT(0);
        }
        __syncthreads();                // everyone's copies for stage s landed

        const uint32_t stb  = sb + (uint32_t)(s * STAGE_BYTES);
        const uint32_t aB   = stb + OFF_A + aRow * A_STRIDE + aColB;
        const uint32_t bB   = stb + OFF_W + nRow * A_STRIDE + bColB;

        #pragma unroll
        for (int c = 0; c < 4; c++) {        // k-chunks of 16
            uint32_t a0, a1, a2, a3;
            LDSM_X4(a0, a1, a2, a3, aB + c * 32);
            #pragma unroll
            for (int p = 0; p < 4; p++) {    // n-tile pairs
                uint32_t b0, b1, b2, b3;
                LDSM_X4(b0, b1, b2, b3, bB + p * 16 * A_STRIDE + c * 32);
                MMA16816(acc[2*p],     a0, a1, a2, a3, b0, b1);
                MMA16816(acc[2*p + 1], a0, a1, a2, a3, b2, b3);
            }
        }
    }

    // epilogue: D fragment -> gmem
    const int rA = row0 + wid * 16 + (lane >> 2);
    const int rB = rA + 8;
    const int c0 = (lane & 3) * 2;
    #pragma unroll
    for (int t = 0; t < 8; t++) {
        int col = t * 8 + c0;
        if (rA < Mm) *reinterpret_cast<float2*>(&out[rA * 64 + col]) = make_float2(acc[t][0], acc[t][1]);
        if (rB < Mm) *reinterpret_cast<float2*>(&out[rB * 64 + col]) = make_float2(acc[t][2], acc[t][3]);
    }
}

// ---------------- BN stats (deterministic 2-stage reduction) -------------------
__global__ __launch_bounds__(256) void stats_kernel(int sel) {
    __shared__ float ssum[256];
    __shared__ float ssq[256];
    const float* x = (sel == 1) ? g_f1 : g_f2;
    const int tid = threadIdx.x;
    const int c   = tid & 63;
    const int g   = tid >> 6;
    const int r0  = blockIdx.x * ROWS_PER_STATB;
    float s = 0.f, q = 0.f;
    for (int r = g; r < ROWS_PER_STATB; r += 4) {
        float v = x[(r0 + r) * 64 + c];
        s += v;
        q += v * v;
    }
    ssum[tid] = s; ssq[tid] = q;
    __syncthreads();
    if (g == 0) {
        float S = ssum[c] + ssum[64 + c] + ssum[128 + c] + ssum[192 + c];
        float Q = ssq[c]  + ssq[64 + c]  + ssq[128 + c]  + ssq[192 + c];
        g_part[blockIdx.x * 128 + c]      = S;
        g_part[blockIdx.x * 128 + 64 + c] = Q;
    }
}

__global__ void finalize_bn_kernel(const float* __restrict__ gamma,
                                   const float* __restrict__ beta) {
    int c = threadIdx.x;
    if (c >= 64) return;
    float S = 0.f, Q = 0.f;
    for (int i = 0; i < NSTATB; i++) {
        S += g_part[i * 128 + c];
        Q += g_part[i * 128 + 64 + c];
    }
    const float invM = 1.0f / (float)Mm;
    float mu  = S * invM;
    float var = Q * invM - mu * mu;
    float rs  = rsqrtf(var + EPSF);
    float sc  = gamma[c] * rs;
    g_scale[c] = sc;
    g_shift[c] = beta[c] - mu * sc;
}

// ---------------- sampling + fused BN2 + mean + proj + index emit --------------
__global__ __launch_bounds__(64) void sampler_kernel(const float* __restrict__ keypoints,
                                                     const float* __restrict__ query,
                                                     const float* __restrict__ projW,
                                                     const float* __restrict__ projb,
                                                     float* __restrict__ out,
                                                     int write_indices) {
    __shared__ int   s_sidx[Kk];
    __shared__ float s_fused[64];
    const int bn  = blockIdx.x;
    const int b   = bn / Nn;
    const int tid = threadIdx.x;

    if (tid < Kk) {
        const float* kp = keypoints + (bn * Kk + tid) * 3;
        int qx = (int)(kp[0] * 2.0f);
        int qy = (int)(kp[1] * 2.0f);
        int qz = (int)(kp[2] * 2.0f);
        qx = min(max(qx, 0), GX - 1);
        qy = min(max(qy, 0), GY - 1);
        qz = min(max(qz, 0), GZ - 1);
        int idx = g_grid[b * CELLS + (qx * GY + qy) * GZ + qz];
        s_sidx[tid] = idx < 0 ? 0 : idx;
        if (write_indices) {
            float* o = out + Bb * Nn * Cc + (bn * Kk + tid) * 4;
            o[0] = (float)b;
            o[1] = (float)qx;
            o[2] = (float)qy;
            o[3] = (float)qz;
        }
    }
    __syncthreads();
    const float sc = g_scale[tid];
    const float sh = g_shift[tid];
    float acc = 0.f;
    #pragma unroll
    for (int k = 0; k < Kk; k++) {
        float v = g_f2[s_sidx[k] * 64 + tid];
        acc += fmaxf(0.f, v * sc + sh);
    }
    float fused = acc * (1.0f / (float)Kk) + query[bn * 64 + tid];
    s_fused[tid] = fused;
    __syncthreads();
    float o = projb[tid];
    const float* wr = projW + tid * 64;
    #pragma unroll
    for (int j = 0; j < 64; j++) o += s_fused[j] * wr[j];
    out[bn * 64 + tid] = o;
}

// ---------------- launch --------------------------------------------------------
extern "C" void kernel_launch(void* const* d_in, const int* in_sizes, int n_in,
                              void* d_out, int out_size) {
    const float* keypoints = (const float*)d_in[0];
    const float* query     = (const float*)d_in[1];
    const float* vfeat     = (const float*)d_in[2];
    const int*   vcoords   = (const int*)  d_in[3];
    const float* W1        = (const float*)d_in[4];
    const float* g1        = (const float*)d_in[5];
    const float* b1        = (const float*)d_in[6];
    const float* W2        = (const float*)d_in[7];
    const float* g2        = (const float*)d_in[8];
    const float* b2        = (const float*)d_in[9];
    const float* pW        = (const float*)d_in[10];
    const float* pb        = (const float*)d_in[11];
    float* out = (float*)d_out;

    cudaFuncSetAttribute(conv_mma_kernel, cudaFuncAttributeMaxDynamicSharedMemorySize, CONV_SMEM);

    init_grid_kernel<<<(Bb * CELLS + 255) / 256, 256>>>();
    scatter_kernel<<<(Mm + 255) / 256, 256>>>(vcoords);
    build_nbr_kernel<<<(Mm + 255) / 256, 256>>>(vcoords);

    // conv1: convert raw features + W1 -> HMMA conv -> g_f1 (pre-BN)
    wprep_kernel<<<(27 * 4096 + 255) / 256, 256>>>(W1);
    split_kernel<<<(Mm * 16 + 255) / 256, 256>>>(vfeat, 0);
    conv_mma_kernel<<<NT_TILES, 256, CONV_SMEM>>>(1);
    stats_kernel<<<NSTATB, 256>>>(1);
    finalize_bn_kernel<<<1, 64>>>(g1, b1);

    // conv2: convert BN1(g_f1)+ReLU + W2 -> HMMA conv -> g_f2 (pre-BN)
    wprep_kernel<<<(27 * 4096 + 255) / 256, 256>>>(W2);
    split_kernel<<<(Mm * 16 + 255) / 256, 256>>>(vfeat, 1);
    conv_mma_kernel<<<NT_TILES, 256, CONV_SMEM>>>(2);
    stats_kernel<<<NSTATB, 256>>>(2);
    finalize_bn_kernel<<<1, 64>>>(g2, b2);

    int write_indices = (out_size >= Bb * Nn * Cc + Bb * Nn * Kk * 4) ? 1 : 0;
    sampler_kernel<<<Bb * Nn, 64>>>(keypoints, query, pW, pb, out, write_indices);
}

// round 16
// speedup vs baseline: 3.6853x; 1.0131x over previous
#include <cuda_runtime.h>
#include <cuda_fp16.h>
#include <cstdint>

#define Bb 2
#define Vv 100000
#define Mm 200000          // B*V
#define Nn 8192
#define Kk 8
#define Cc 64
#define GX 128
#define GY 128
#define GZ 16
#define CELLS (GX*GY*GZ)
#define EPSF 1e-5f
#define NT2 ((Mm + 255) / 256)        // 782 conv tiles (256 rows each)

// smem stage layout (144B-padded rows; 144B = 36 banks -> conflict-free ldmatrix)
#define A_STRIDE 144
#define OFF_A 0
#define OFF_W 36864                   // 256 rows * 144B
#define STAGE_BYTES 46080             // + 64 rows * 144B
#define CONV_SMEM (2 * STAGE_BYTES)   // 92160

// ---------------- scratch (device globals; only referenced from device code) ---
__device__ int   g_grid[Bb * CELLS];
__device__ int   g_nbr[Mm * 27];
__device__ float g_f1[Mm * Cc];
__device__ float g_f2[Mm * Cc];
__device__ float g_part[NT2 * 128];   // per-tile [sum(64), sumsq(64)]
__device__ __align__(16) float g_scale[Cc];
__device__ __align__(16) float g_shift[Cc];
__device__ __align__(16) __half g_a16[Mm * Cc];          // fp16 features
__device__ __align__(16) __half g_wt16[27 * 64 * 64];    // [k][cout][cin] fp16

__device__ __forceinline__ uint32_t smem_u32(const void* p) {
    uint32_t a;
    asm("{ .reg .u64 t; cvta.to.shared.u64 t, %1; cvt.u32.u64 %0, t; }" : "=r"(a) : "l"(p));
    return a;
}
#define LDSM_X4(r0, r1, r2, r3, addr) \
    asm volatile("ldmatrix.sync.aligned.m8n8.x4.shared.b16 {%0,%1,%2,%3}, [%4];" \
        : "=r"(r0), "=r"(r1), "=r"(r2), "=r"(r3) : "r"(addr))
#define MMA16816(d, a0, a1, a2, a3, b0, b1) \
    asm("mma.sync.aligned.m16n8k16.row.col.f32.f16.f16.f32 " \
        "{%0,%1,%2,%3}, {%4,%5,%6,%7}, {%8,%9}, {%0,%1,%2,%3};" \
        : "+f"((d)[0]), "+f"((d)[1]), "+f"((d)[2]), "+f"((d)[3]) \
        : "r"(a0), "r"(a1), "r"(a2), "r"(a3), "r"(b0), "r"(b1))
#define CP_ASYNC16(smem, gptr, sz) \
    asm volatile("cp.async.cg.shared.global [%0], [%1], 16, %2;" \
        :: "r"((uint32_t)(smem)), "l"(gptr), "r"((uint32_t)(sz)) : "memory")
#define CP_COMMIT() asm volatile("cp.async.commit_group;" ::: "memory")
#define CP_WAIT(n)  asm volatile("cp.async.wait_group %0;" :: "n"(n) : "memory")

// ---------------- grid init / scatter / neighbor table ------------------------
__global__ void init_grid_kernel() {
    int i = blockIdx.x * blockDim.x + threadIdx.x;
    if (i < Bb * CELLS) g_grid[i] = -1;
}

__global__ void scatter_kernel(const int* __restrict__ coords) {
    int m = blockIdx.x * blockDim.x + threadIdx.x;
    if (m >= Mm) return;
    int b = m / Vv;
    g_grid[b * CELLS + (coords[m*3] * GY + coords[m*3+1]) * GZ + coords[m*3+2]] = m;
}

__global__ void build_nbr_kernel(const int* __restrict__ coords) {
    int m = blockIdx.x * blockDim.x + threadIdx.x;
    if (m >= Mm) return;
    int b = m / Vv;
    int cx = coords[m*3], cy = coords[m*3+1], cz = coords[m*3+2];
    const int* gb = g_grid + b * CELLS;
    int k = 0;
    #pragma unroll
    for (int dx = -1; dx <= 1; dx++)
      #pragma unroll
      for (int dy = -1; dy <= 1; dy++)
        #pragma unroll
        for (int dz = -1; dz <= 1; dz++) {
            int nx = cx + dx, ny = cy + dy, nz = cz + dz;
            int idx = -1;
            if (nx >= 0 && nx < GX && ny >= 0 && ny < GY && nz >= 0 && nz < GZ)
                idx = gb[(nx * GY + ny) * GZ + nz];
            g_nbr[m * 27 + k] = idx;
            k++;
        }
}

// ---------------- weight prep: transpose + fp16 convert ------------------------
__global__ void wprep_kernel(const float* __restrict__ W) {
    int i = blockIdx.x * blockDim.x + threadIdx.x;
    if (i >= 27 * 4096) return;
    int k = i >> 12, r = i & 4095;
    int n = r >> 6, kkk = r & 63;
    g_wt16[i] = __float2half(W[k * 4096 + kkk * 64 + n]);   // [k][cin][cout] -> [k][cout][cin]
}

// ---------------- feature prep: (optional BN1+ReLU) + fp16 convert -------------
__global__ __launch_bounds__(256) void split_kernel(const float* __restrict__ ext, int mode) {
    int i4 = blockIdx.x * blockDim.x + threadIdx.x;   // float4 index
    if (i4 >= Mm * 16) return;
    const float4* s = (mode == 0) ? (const float4*)ext : (const float4*)g_f1;
    float4 v = s[i4];
    if (mode == 1) {
        int c0 = (i4 & 15) * 4;
        v.x = fmaxf(0.f, v.x * g_scale[c0+0] + g_shift[c0+0]);
        v.y = fmaxf(0.f, v.y * g_scale[c0+1] + g_shift[c0+1]);
        v.z = fmaxf(0.f, v.z * g_scale[c0+2] + g_shift[c0+2]);
        v.w = fmaxf(0.f, v.w * g_scale[c0+3] + g_shift[c0+3]);
    }
    __half2 p0 = __halves2half2(__float2half(v.x), __float2half(v.y));
    __half2 p1 = __halves2half2(__float2half(v.z), __float2half(v.w));
    uint2 u;
    u.x = *reinterpret_cast<uint32_t*>(&p0);
    u.y = *reinterpret_cast<uint32_t*>(&p1);
    reinterpret_cast<uint2*>(g_a16)[i4] = u;
}

// ---------------- HMMA conv: 256-row tile, 27 offsets, cp.async double-buffer --
// 8 warps; warp w owns rows w*16..w*16+15 and 128+w*16..128+w*16+15.
// Fused BN-stat partials (per-tile sum/sumsq per channel) in the epilogue.
__global__ __launch_bounds__(256, 2) void conv_mma_kernel(int dst_sel) {
    extern __shared__ char smem[];
    const int tid  = threadIdx.x;
    const int wid  = tid >> 5;
    const int lane = tid & 31;
    const int row0 = blockIdx.x * 256;
    float* out = (dst_sel == 1) ? g_f1 : g_f2;

    const uint32_t sb = smem_u32(smem);

    // per-lane ldmatrix address components
    const int row_in = lane & 7;
    const int aRow   = wid * 16 + ((lane >> 3) & 1) * 8 + row_in;   // mtile0 row
    const int aColB  = (lane >> 4) * 16;
    const int nRow   = ((lane >> 4) & 1) * 8 + row_in;
    const int bColB  = ((lane >> 3) & 1) * 16;

    float acc0[8][4], acc1[8][4];
    #pragma unroll
    for (int t = 0; t < 8; t++)
        #pragma unroll
        for (int j = 0; j < 4; j++) { acc0[t][j] = 0.f; acc1[t][j] = 0.f; }

    const int aCh = tid & 7;

    // issue cp.async for offset k into stage s (A: 2048 slots, W: 512 slots)
    auto issue_stage = [&](int k, int s) {
        uint32_t stb = sb + (uint32_t)(s * STAGE_BYTES);
        #pragma unroll
        for (int ss = 0; ss < 8; ss++) {
            int row = (tid + ss * 256) >> 3;
            int rg  = row0 + row;
            int idx = (rg < Mm) ? g_nbr[rg * 27 + k] : -1;
            uint32_t sz = (idx >= 0) ? 16u : 0u;
            long off = (idx >= 0) ? (long)idx * 64 + aCh * 8 : 0;
            CP_ASYNC16(stb + OFF_A + (uint32_t)(row * A_STRIDE + aCh * 16),
                       (const char*)&g_a16[off], sz);
        }
        #pragma unroll
        for (int ss = 0; ss < 2; ss++) {
            int n = (tid + ss * 256) >> 3;
            CP_ASYNC16(stb + OFF_W + (uint32_t)(n * A_STRIDE + aCh * 16),
                       (const char*)&g_wt16[k * 4096 + n * 64 + aCh * 8], 16u);
        }
        CP_COMMIT();
    };

    issue_stage(0, 0);

    for (int k = 0; k < 27; k++) {
        const int s = k & 1;
        if (k + 1 < 27) {
            __syncthreads();            // all warps done MMA(k-1) on stage s^1
            issue_stage(k + 1, s ^ 1);
            CP_WAIT(1);
        } else {
            CP_WAIT(0);
        }
        __syncthreads();

        const uint32_t stb = sb + (uint32_t)(s * STAGE_BYTES);
        const uint32_t aB0 = stb + OFF_A + aRow * A_STRIDE + aColB;
        const uint32_t aB1 = aB0 + 128 * A_STRIDE;
        const uint32_t bB  = stb + OFF_W + nRow * A_STRIDE + bColB;

        #pragma unroll
        for (int c = 0; c < 4; c++) {        // k-chunks of 16
            uint32_t x0, x1, x2, x3, y0, y1, y2, y3;
            LDSM_X4(x0, x1, x2, x3, aB0 + c * 32);
            LDSM_X4(y0, y1, y2, y3, aB1 + c * 32);
            #pragma unroll
            for (int p = 0; p < 4; p++) {    // n-tile pairs (B reused across mtiles)
                uint32_t b0, b1, b2, b3;
                LDSM_X4(b0, b1, b2, b3, bB + p * 16 * A_STRIDE + c * 32);
                MMA16816(acc0[2*p],     x0, x1, x2, x3, b0, b1);
                MMA16816(acc0[2*p + 1], x0, x1, x2, x3, b2, b3);
                MMA16816(acc1[2*p],     y0, y1, y2, y3, b0, b1);
                MMA16816(acc1[2*p + 1], y0, y1, y2, y3, b2, b3);
            }
        }
    }

    // ---- epilogue: write outputs ----
    const int rA0 = row0 + wid * 16 + (lane >> 2);
    const int c0  = (lane & 3) * 2;
    #pragma unroll
    for (int t = 0; t < 8; t++) {
        int col = t * 8 + c0;
        if (rA0 < Mm)       *reinterpret_cast<float2*>(&out[rA0 * 64 + col])         = make_float2(acc0[t][0], acc0[t][1]);
        if (rA0 + 8 < Mm)   *reinterpret_cast<float2*>(&out[(rA0 + 8) * 64 + col])   = make_float2(acc0[t][2], acc0[t][3]);
        if (rA0 + 128 < Mm) *reinterpret_cast<float2*>(&out[(rA0 + 128) * 64 + col]) = make_float2(acc1[t][0], acc1[t][1]);
        if (rA0 + 136 < Mm) *reinterpret_cast<float2*>(&out[(rA0 + 136) * 64 + col]) = make_float2(acc1[t][2], acc1[t][3]);
    }

    // ---- fused BN stats: per-channel sum/sumsq over this tile's 256 rows ----
    // rows >= Mm contribute exact zeros (A was zero-filled), so no guard needed.
    float ps[8][2], pq[8][2];
    #pragma unroll
    for (int t = 0; t < 8; t++) {
        #pragma unroll
        for (int j = 0; j < 2; j++) {
            float v0 = acc0[t][j], v1 = acc0[t][j + 2];
            float w0 = acc1[t][j], w1 = acc1[t][j + 2];
            ps[t][j] = v0 + v1 + w0 + w1;
            pq[t][j] = v0 * v0 + v1 * v1 + w0 * w0 + w1 * w1;
        }
    }
    #pragma unroll
    for (int off = 4; off < 32; off <<= 1) {
        #pragma unroll
        for (int t = 0; t < 8; t++) {
            #pragma unroll
            for (int j = 0; j < 2; j++) {
                ps[t][j] += __shfl_xor_sync(0xFFFFFFFFu, ps[t][j], off);
                pq[t][j] += __shfl_xor_sync(0xFFFFFFFFu, pq[t][j], off);
            }
        }
    }
    float* s_stat = reinterpret_cast<float*>(smem);   // [8 warps][128]
    __syncthreads();                                  // done reading stages
    if (lane < 4) {
        #pragma unroll
        for (int t = 0; t < 8; t++) {
            #pragma unroll
            for (int j = 0; j < 2; j++) {
                int ch = t * 8 + lane * 2 + j;
                s_stat[wid * 128 + ch]      = ps[t][j];
                s_stat[wid * 128 + 64 + ch] = pq[t][j];
            }
        }
    }
    __syncthreads();
    if (tid < 128) {
        float v = 0.f;
        #pragma unroll
        for (int w = 0; w < 8; w++) v += s_stat[w * 128 + tid];
        g_part[blockIdx.x * 128 + tid] = v;
    }
}

// ---------------- finalize BN over per-tile partials ---------------------------
__global__ void finalize_bn_kernel(const float* __restrict__ gamma,
                                   const float* __restrict__ beta) {
    int c = threadIdx.x;
    if (c >= 64) return;
    float S = 0.f, Q = 0.f;
    for (int i = 0; i < NT2; i++) {
        S += g_part[i * 128 + c];
        Q += g_part[i * 128 + 64 + c];
    }
    const float invM = 1.0f / (float)Mm;
    float mu  = S * invM;
    float var = Q * invM - mu * mu;
    float rs  = rsqrtf(var + EPSF);
    float sc  = gamma[c] * rs;
    g_scale[c] = sc;
    g_shift[c] = beta[c] - mu * sc;
}

// ---------------- sampling + fused BN2 + mean + proj + index emit --------------
__global__ __launch_bounds__(64) void sampler_kernel(const float* __restrict__ keypoints,
                                                     const float* __restrict__ query,
                                                     const float* __restrict__ projW,
                                                     const float* __restrict__ projb,
                                                     float* __restrict__ out,
                                                     int write_indices) {
    __shared__ int   s_sidx[Kk];
    __shared__ float s_fused[64];
    const int bn  = blockIdx.x;
    const int b   = bn / Nn;
    const int tid = threadIdx.x;

    if (tid < Kk) {
        const float* kp = keypoints + (bn * Kk + tid) * 3;
        int qx = (int)(kp[0] * 2.0f);
        int qy = (int)(kp[1] * 2.0f);
        int qz = (int)(kp[2] * 2.0f);
        qx = min(max(qx, 0), GX - 1);
        qy = min(max(qy, 0), GY - 1);
        qz = min(max(qz, 0), GZ - 1);
        int idx = g_grid[b * CELLS + (qx * GY + qy) * GZ + qz];
        s_sidx[tid] = idx < 0 ? 0 : idx;
        if (write_indices) {
            float* o = out + Bb * Nn * Cc + (bn * Kk + tid) * 4;
            o[0] = (float)b;
            o[1] = (float)qx;
            o[2] = (float)qy;
            o[3] = (float)qz;
        }
    }
    __syncthreads();
    const float sc = g_scale[tid];
    const float sh = g_shift[tid];
    float acc = 0.f;
    #pragma unroll
    for (int k = 0; k < Kk; k++) {
        float v = g_f2[s_sidx[k] * 64 + tid];
        acc += fmaxf(0.f, v * sc + sh);
    }
    float fused = acc * (1.0f / (float)Kk) + query[bn * 64 + tid];
    s_fused[tid] = fused;
    __syncthreads();
    float o = projb[tid];
    const float* wr = projW + tid * 64;
    #pragma unroll
    for (int j = 0; j < 64; j++) o += s_fused[j] * wr[j];
    out[bn * 64 + tid] = o;
}

// ---------------- launch --------------------------------------------------------
extern "C" void kernel_launch(void* const* d_in, const int* in_sizes, int n_in,
                              void* d_out, int out_size) {
    const float* keypoints = (const float*)d_in[0];
    const float* query     = (const float*)d_in[1];
    const float* vfeat     = (const float*)d_in[2];
    const int*   vcoords   = (const int*)  d_in[3];
    const float* W1        = (const float*)d_in[4];
    const float* g1        = (const float*)d_in[5];
    const float* b1        = (const float*)d_in[6];
    const float* W2        = (const float*)d_in[7];
    const float* g2        = (const float*)d_in[8];
    const float* b2        = (const float*)d_in[9];
    const float* pW        = (const float*)d_in[10];
    const float* pb        = (const float*)d_in[11];
    float* out = (float*)d_out;

    cudaFuncSetAttribute(conv_mma_kernel, cudaFuncAttributeMaxDynamicSharedMemorySize, CONV_SMEM);

    init_grid_kernel<<<(Bb * CELLS + 255) / 256, 256>>>();
    scatter_kernel<<<(Mm + 255) / 256, 256>>>(vcoords);
    build_nbr_kernel<<<(Mm + 255) / 256, 256>>>(vcoords);

    // conv1: convert raw features + W1 -> HMMA conv (+stats) -> g_f1 (pre-BN)
    wprep_kernel<<<(27 * 4096 + 255) / 256, 256>>>(W1);
    split_kernel<<<(Mm * 16 + 255) / 256, 256>>>(vfeat, 0);
    conv_mma_kernel<<<NT2, 256, CONV_SMEM>>>(1);
    finalize_bn_kernel<<<1, 64>>>(g1, b1);

    // conv2: convert BN1(g_f1)+ReLU + W2 -> HMMA conv (+stats) -> g_f2 (pre-BN)
    wprep_kernel<<<(27 * 4096 + 255) / 256, 256>>>(W2);
    split_kernel<<<(Mm * 16 + 255) / 256, 256>>>(vfeat, 1);
    conv_mma_kernel<<<NT2, 256, CONV_SMEM>>>(2);
    finalize_bn_kernel<<<1, 64>>>(g2, b2);

    int write_indices = (out_size >= Bb * Nn * Cc + Bb * Nn * Kk * 4) ? 1 : 0;
    sampler_kernel<<<Bb * Nn, 64>>>(keypoints, query, pW, pb, out, write_indices);
}